// round 17
// baseline (speedup 1.0000x reference)
#include <cuda_runtime.h>

// Problem shape (fixed by the dataset)
#define BB 16
#define NN 8192
#define FF 256
#define ROW4 64                       // float4s per row (FF/4)
#define NROWS (BB * NN)               // 131072
#define SLAB8 8                       // rows per work-unit slab
#define NSLAB8 (NROWS / SLAB8)        // 16384 slabs
#define NUNIT (NSLAB8 * 2)            // 32768 (slab, half) units
#define NBLK 148                      // one block per SM (wave-1 co-resident -> spin is safe)
#define NT 1024                       // 32 warps per block
#define EPS 1e-3f

// Scratch (allocation-free rule: __device__ globals)
__device__ __align__(16) float g_part[NBLK * 2 * FF];
__device__ __align__(16) float g_scale[FF];
__device__ __align__(16) float g_shift[FF];

// Reset-safe grid barrier state (returns to all-zero at the end of every launch,
// so graph replays see identical initial state).
__device__ int g_ctr0, g_flag0, g_ack0;
__device__ int g_ctr1, g_flag1, g_ack1;

__device__ __forceinline__ void grid_bar(int* ctr, int* flag, int* ack) {
    __threadfence();                               // publish my stores (L2)
    int p = atomicAdd(ctr, 1);
    if (p == NBLK - 1) atomicExch(flag, 1);        // last arriver releases
    while (atomicAdd(flag, 0) == 0) __nanosleep(64);
    int a = atomicAdd(ack, 1);
    if (a == NBLK - 1) {                           // everyone has passed the spin
        *flag = 0; *ctr = 0; *ack = 0;
        __threadfence();
    }
}

__global__ __launch_bounds__(NT, 1)
void mbn_fused_kernel(const float4* __restrict__ x,
                      const int* __restrict__ nv,
                      const float* __restrict__ gamma,
                      const float* __restrict__ beta,
                      float4* __restrict__ out) {
    __shared__ int   s_nv[BB];
    __shared__ float s_buf[4 * NT];                // 16 KB: reduction scratch (A), combine (B)

    int tid  = threadIdx.x;
    int lane = tid & 31;
    int gw   = blockIdx.x * (NT >> 5) + (tid >> 5);
    const int W = NBLK * (NT >> 5);                // 4736 warps chip-wide (even)
    const int h = gw & 1;                          // fixed half per warp (W even)
    const int colo = h * 32 + lane;                // my float4 column, fixed forever

    if (tid < BB) s_nv[tid] = nv[tid];
    __syncthreads();

    const float4 z4 = make_float4(0.f, 0.f, 0.f, 0.f);

    // ================= Phase A: masked sum/sumsq + padded-region zero stores =================
    // The zeros of the output don't depend on the statistics, so the invalid-row
    // stores ride here, overlapping the otherwise write-idle read phase.
    {
        float s0 = 0.f, s1 = 0.f, s2 = 0.f, s3 = 0.f;
        float q0 = 0.f, q1 = 0.f, q2 = 0.f, q3 = 0.f;

        for (int u = gw; u < NUNIT; u += W) {
            int s    = u >> 1;
            int row0 = s << 3;                    // * SLAB8
            int n    = row0 & (NN - 1);
            int b    = row0 >> 13;
            int nvb  = s_nv[b];
            size_t off = (size_t)row0 * ROW4 + colo;
            const float4* p  = x + off;
            float4*       po = out + off;
            if (n + SLAB8 <= nvb) {
                float4 v[SLAB8];
                #pragma unroll
                for (int r = 0; r < SLAB8; r++)   // loads first (batched)
                    v[r] = __ldcg(p + r * ROW4);
                #pragma unroll
                for (int r = 0; r < SLAB8; r++) { // then consume
                    s0 += v[r].x; s1 += v[r].y; s2 += v[r].z; s3 += v[r].w;
                    q0 += v[r].x * v[r].x; q1 += v[r].y * v[r].y;
                    q2 += v[r].z * v[r].z; q3 += v[r].w * v[r].w;
                }
            } else if (n >= nvb) {
                // Fully padded: zero-store the output now (no loads).
                #pragma unroll
                for (int r = 0; r < SLAB8; r++)
                    __stcs(po + r * ROW4, z4);
            } else {
                // Boundary (<=32 units total): accumulate valid rows, zero the tail.
                int cnt = nvb - n;                // 1..7
                for (int r = 0; r < cnt; r++) {
                    float4 v = __ldcg(p + r * ROW4);
                    s0 += v.x; s1 += v.y; s2 += v.z; s3 += v.w;
                    q0 += v.x * v.x; q1 += v.y * v.y;
                    q2 += v.z * v.z; q3 += v.w * v.w;
                }
                for (int r = cnt; r < SLAB8; r++)
                    __stcs(po + r * ROW4, z4);
            }
        }

        // Cross-warp reduction (2 rounds), conflict-free; STORE partials (no atomics).
        float* myPart = &g_part[(size_t)blockIdx.x * (2 * FF)];
        #define RED_ROUND(v0, v1, v2, v3, foff)                                   \
            s_buf[0 * NT + tid] = v0; s_buf[1 * NT + tid] = v1;                   \
            s_buf[2 * NT + tid] = v2; s_buf[3 * NT + tid] = v3;                   \
            __syncthreads();                                                      \
            if (tid < 256) {                                                      \
                int l = tid & 31, rest = tid >> 5;                                \
                int j = rest & 3, hh = rest >> 2;                                 \
                float t = 0.f;                                                    \
                _Pragma("unroll")                                                 \
                for (int w = 0; w < 16; w++)                                      \
                    t += s_buf[j * NT + (2 * w + hh) * 32 + l];                   \
                myPart[(foff) + hh * 128 + 4 * l + j] = t;                        \
            }                                                                     \
            __syncthreads();

        RED_ROUND(s0, s1, s2, s3, 0)              // sums, features 0..255
        RED_ROUND(q0, q1, q2, q3, FF)             // sumsqs
        #undef RED_ROUND
    }

    // ================= Barrier 0: all partials published =================
    if (tid == 0) grid_bar(&g_ctr0, &g_flag0, &g_ack0);
    __syncthreads();

    // ================= Phase B: block 0 reduces partials + finalize =================
    if (blockIdx.x == 0) {
        __threadfence();
        float* s_sum = s_buf;                      // [4][FF]
        float* s_sq  = s_buf + 4 * FF;             // [4][FF]
        int c = tid >> 8;                          // 0..3
        int f = tid & 255;
        float sum = 0.f, sumsq = 0.f;
        int b0 = c * 37;                           // 148 = 4 * 37
        #pragma unroll 8
        for (int i = 0; i < 37; i++) {
            const float* p = &g_part[(size_t)(b0 + i) * (2 * FF)];
            sum   += __ldcg(&p[f]);
            sumsq += __ldcg(&p[FF + f]);
        }
        s_sum[c * FF + f] = sum;
        s_sq[c * FF + f]  = sumsq;
        __syncthreads();
        if (tid < FF) {
            int cn = 0;
            #pragma unroll
            for (int i = 0; i < BB; i++) cn += s_nv[i];
            float cnt  = fmaxf((float)cn, 1.0f);
            float S = s_sum[0 * FF + tid] + s_sum[1 * FF + tid] +
                      s_sum[2 * FF + tid] + s_sum[3 * FF + tid];
            float Q = s_sq[0 * FF + tid] + s_sq[1 * FF + tid] +
                      s_sq[2 * FF + tid] + s_sq[3 * FF + tid];
            float mean = S / cnt;
            float var  = Q / cnt - mean * mean;
            float inv  = rsqrtf(var + EPS);
            float sc   = inv * gamma[tid];
            g_scale[tid] = sc;
            g_shift[tid] = beta[tid] - mean * sc;
        }
        __syncthreads();
    }

    // ================= Barrier 1: scale/shift published =================
    if (tid == 0) grid_bar(&g_ctr1, &g_flag1, &g_ack1);
    __syncthreads();
    __threadfence();                               // flush L1 before reading g_scale

    // ================= Phase C: normalize VALID rows only =================
    // Padded rows were already zeroed in phase A; invalid units skip in a few cycles.
    {
        const float4 sc = ((const float4*)g_scale)[colo];
        const float4 sh = ((const float4*)g_shift)[colo];

        for (int u = gw; u < NUNIT; u += W) {
            int s    = u >> 1;
            int row0 = s << 3;
            int n    = row0 & (NN - 1);
            int b    = row0 >> 13;
            int nvb  = s_nv[b];
            if (n >= nvb) continue;               // already zeroed in phase A
            size_t off = (size_t)row0 * ROW4 + colo;
            const float4* p  = x + off;
            float4*       po = out + off;

            if (n + SLAB8 <= nvb) {
                float4 v[SLAB8];
                #pragma unroll
                for (int r = 0; r < SLAB8; r++)   // batched loads
                    v[r] = p[r * ROW4];
                #pragma unroll
                for (int r = 0; r < SLAB8; r++) {
                    float4 ra;
                    ra.x = fmaf(v[r].x, sc.x, sh.x);
                    ra.y = fmaf(v[r].y, sc.y, sh.y);
                    ra.z = fmaf(v[r].z, sc.z, sh.z);
                    ra.w = fmaf(v[r].w, sc.w, sh.w);
                    __stcs(po + r * ROW4, ra);
                }
            } else {
                int cnt = nvb - n;                // 1..7 valid rows; tail already zeroed
                for (int r = 0; r < cnt; r++) {
                    float4 v = p[r * ROW4];
                    float4 ra;
                    ra.x = fmaf(v.x, sc.x, sh.x);
                    ra.y = fmaf(v.y, sc.y, sh.y);
                    ra.z = fmaf(v.z, sc.z, sh.z);
                    ra.w = fmaf(v.w, sc.w, sh.w);
                    __stcs(po + r * ROW4, ra);
                }
            }
        }
    }
}

extern "C" void kernel_launch(void* const* d_in, const int* in_sizes, int n_in,
                              void* d_out, int out_size) {
    const float4* x     = (const float4*)d_in[0];   // voxel_features [16,8192,256]
    const int*    nv    = (const int*)d_in[1];      // num_valid_voxels [16]
    const float*  gamma = (const float*)d_in[2];    // [256]
    const float*  beta  = (const float*)d_in[3];    // [256]
    float4*       out   = (float4*)d_out;

    mbn_fused_kernel<<<NBLK, NT>>>(x, nv, gamma, beta, out);
}